// round 12
// baseline (speedup 1.0000x reference)
#include <cuda_runtime.h>
#include <cuda_bf16.h>
#include <cstdint>

#define B_  2
#define L_  512
#define D_  1024
#define E_  32      // INNER
#define P_  128     // PAIR

// Global scratch (allocation-free rule: __device__ globals)
__device__ float    g_k  [B_ * L_ * E_];        // [b*L + i][e]  fp32
__device__ uint32_t g_qh [B_ * L_ * 16];        // [row][16] bf16x2 hi
__device__ uint32_t g_ql [B_ * L_ * 16];        // [row][16] bf16x2 lo
__device__ uint32_t g_Mh [B_ * L_ * P_ * 16];   // [i][p][16] bf16x2 hi
__device__ uint32_t g_Ml [B_ * L_ * P_ * 16];   // [i][p][16] bf16x2 lo
__device__ float    g_C  [B_ * L_ * P_];        // [i][p]

// ---------------------------------------------------------------------------
// helpers
// ---------------------------------------------------------------------------
__device__ __forceinline__ uint32_t smem_u32(const void* p) {
    uint32_t a;
    asm("{ .reg .u64 t; cvta.to.shared.u64 t, %1; cvt.u32.u64 %0, t; }"
        : "=r"(a) : "l"(p));
    return a;
}

__device__ __forceinline__ void mma16(float* d, const uint32_t* a, uint32_t b0, uint32_t b1) {
    asm volatile(
        "mma.sync.aligned.m16n8k16.row.col.f32.bf16.bf16.f32 "
        "{%0,%1,%2,%3}, {%4,%5,%6,%7}, {%8,%9}, {%0,%1,%2,%3};"
        : "+f"(d[0]), "+f"(d[1]), "+f"(d[2]), "+f"(d[3])
        : "r"(a[0]), "r"(a[1]), "r"(a[2]), "r"(a[3]), "r"(b0), "r"(b1));
}

__device__ __forceinline__ void ldsm4(uint32_t* r, uint32_t addr) {
    asm volatile("ldmatrix.sync.aligned.m8n8.x4.shared.b16 {%0,%1,%2,%3}, [%4];"
                 : "=r"(r[0]), "=r"(r[1]), "=r"(r[2]), "=r"(r[3]) : "r"(addr));
}

__device__ __forceinline__ void cpa16(uint32_t saddr, const void* g) {
    asm volatile("cp.async.cg.shared.global [%0], [%1], 16;"
                 :: "r"(saddr), "l"(g) : "memory");
}
#define CPA_COMMIT() asm volatile("cp.async.commit_group;" ::: "memory")
#define CPA_WAIT0()  asm volatile("cp.async.wait_group 0;" ::: "memory")

// bf16 hi/lo split of two floats, packed into two words
__device__ __forceinline__ void split2(float a, float b, uint32_t& hw, uint32_t& lw) {
    __nv_bfloat16 ah = __float2bfloat16(a);
    __nv_bfloat16 bh = __float2bfloat16(b);
    __nv_bfloat16 al = __float2bfloat16(a - __bfloat162float(ah));
    __nv_bfloat16 bl = __float2bfloat16(b - __bfloat162float(bh));
    hw = (uint32_t)__bfloat16_as_ushort(ah) | ((uint32_t)__bfloat16_as_ushort(bh) << 16);
    lw = (uint32_t)__bfloat16_as_ushort(al) | ((uint32_t)__bfloat16_as_ushort(bl) << 16);
}

// ---------------------------------------------------------------------------
// Kernel 1: LayerNorm + projection -> q (pre-split bf16 hi/lo), k (fp32)
// grid (128, 2), 256 threads: CTA = 8 rows x 32 outputs (y: q-half/k-half)
// Warp proj map: 4 o x 8 part -> 4-lane LDS dedup (1 phase per LDS.128).
// ---------------------------------------------------------------------------
__global__ __launch_bounds__(256, 4)
void ln_proj_kernel(const float* __restrict__ x,
                    const float* __restrict__ gamma,
                    const float* __restrict__ beta,
                    const float* __restrict__ Wp,   // [64][1024]
                    const float* __restrict__ bp) { // [64]
    __shared__ float sn[8][D_];         // 32 KB
    __shared__ float sq[8][32];
    const int tid = threadIdx.x;
    const int wid = tid >> 5;
    const int lid = tid & 31;
    const int row = blockIdx.x * 8 + wid;
    const int ohalf = blockIdx.y;       // 0 -> q outs, 1 -> k outs

    {
        const float4* xr = reinterpret_cast<const float4*>(x + (size_t)row * D_);
        float4 v[8];
        #pragma unroll
        for (int u = 0; u < 8; u++) v[u] = xr[lid + 32 * u];

        float s = 0.f;
        #pragma unroll
        for (int u = 0; u < 8; u++) s += v[u].x + v[u].y + v[u].z + v[u].w;
        #pragma unroll
        for (int o = 16; o > 0; o >>= 1) s += __shfl_xor_sync(0xffffffffu, s, o);
        const float mu = s * (1.0f / D_);

        float ss = 0.f;
        #pragma unroll
        for (int u = 0; u < 8; u++) {
            float d0 = v[u].x - mu, d1 = v[u].y - mu, d2 = v[u].z - mu, d3 = v[u].w - mu;
            ss += d0 * d0 + d1 * d1 + d2 * d2 + d3 * d3;
        }
        #pragma unroll
        for (int o = 16; o > 0; o >>= 1) ss += __shfl_xor_sync(0xffffffffu, ss, o);
        const float rs = rsqrtf(ss * (1.0f / D_) + 1e-5f);

        const float4* g4 = reinterpret_cast<const float4*>(gamma);
        const float4* b4 = reinterpret_cast<const float4*>(beta);
        #pragma unroll
        for (int u = 0; u < 8; u++) {
            float4 g = g4[lid + 32 * u];
            float4 be = b4[lid + 32 * u];
            float4 o4;
            o4.x = (v[u].x - mu) * rs * g.x + be.x;
            o4.y = (v[u].y - mu) * rs * g.y + be.y;
            o4.z = (v[u].z - mu) * rs * g.z + be.z;
            o4.w = (v[u].w - mu) * rs * g.w + be.w;
            reinterpret_cast<float4*>(sn[wid])[lid + 32 * u] = o4;
        }
    }
    __syncthreads();

    // projection: thread = (o 0..31, part 0..7); 8 rows per thread
    const int o = tid >> 3;
    const int part = tid & 7;
    const int og = ohalf * 32 + o;
    const float4* w4 = reinterpret_cast<const float4*>(Wp + (size_t)og * D_);
    float acc[8];
    #pragma unroll
    for (int r = 0; r < 8; r++) acc[r] = 0.f;

    #pragma unroll 4
    for (int t = 0; t < 32; t++) {
        const int f = part + 8 * t;
        float4 w = w4[f];
        #pragma unroll
        for (int r = 0; r < 8; r++) {
            float4 a = reinterpret_cast<const float4*>(sn[r])[f];
            acc[r] += a.x * w.x + a.y * w.y + a.z * w.z + a.w * w.w;
        }
    }
    #pragma unroll
    for (int r = 0; r < 8; r++) {
        acc[r] += __shfl_xor_sync(0xffffffffu, acc[r], 1);
        acc[r] += __shfl_xor_sync(0xffffffffu, acc[r], 2);
        acc[r] += __shfl_xor_sync(0xffffffffu, acc[r], 4);
    }

    const int row0 = blockIdx.x * 8;
    if (ohalf == 1) {
        if (part == 0) {
            const float bias = bp[og];
            #pragma unroll
            for (int r = 0; r < 8; r++)
                g_k[(size_t)(row0 + r) * E_ + o] = acc[r] + bias;
        }
    } else {
        if (part == 0) {
            const float bias = bp[og];
            #pragma unroll
            for (int r = 0; r < 8; r++)
                sq[r][o] = acc[r] + bias;
        }
        __syncthreads();
        if (tid < 128) {
            const int r = tid >> 4;       // 0..7
            const int w = tid & 15;       // 0..15 word
            uint32_t hw, lw;
            split2(sq[r][2 * w], sq[r][2 * w + 1], hw, lw);
            g_qh[(size_t)(row0 + r) * 16 + w] = hw;
            g_ql[(size_t)(row0 + r) * 16 + w] = lw;
        }
    }
}

// ---------------------------------------------------------------------------
// Kernel 1b: precompute M_i (bf16 hi/lo) + C_i for all i.
// grid 256 x 256 thr; each block stages Wo once, serves 4 i's.
// ---------------------------------------------------------------------------
#define WOPAD 68
__global__ __launch_bounds__(256)
void prep_kernel(const float* __restrict__ Wo,   // [128][64]
                 const float* __restrict__ bo) { // [128]
    __shared__ float sWo[128 * WOPAD];  // 34816 B
    __shared__ float sk[4][E_];
    const int tid = threadIdx.x;

    {
        const float4* wsrc = reinterpret_cast<const float4*>(Wo);
        #pragma unroll
        for (int it = 0; it < 8; it++) {
            const int idx = tid + 256 * it;     // 0..2047
            const int row = idx >> 4;
            const int seg = idx & 15;
            *reinterpret_cast<float4*>(sWo + (size_t)row * WOPAD + seg * 4) = wsrc[idx];
        }
    }
    if (tid < 128) {
        const int ii = tid >> 5;
        const int e  = tid & 31;
        sk[ii][e] = g_k[(size_t)(blockIdx.x * 4 + ii) * E_ + e];
    }
    __syncthreads();

    const int p = tid >> 1;
    const int halfe = tid & 1;
    const float* wrow = sWo + (size_t)p * WOPAD;

    #pragma unroll 1
    for (int ii = 0; ii < 4; ii++) {
        const int i = blockIdx.x * 4 + ii;
        float m[16];
        float cacc = 0.f;
        #pragma unroll
        for (int u = 0; u < 16; u++) {
            const int e = halfe * 16 + u;
            float w1 = wrow[e];
            float w2 = wrow[E_ + e];
            float kv = sk[ii][e];
            m[u] = fmaf(w1, kv, w2);
            cacc += w2 * kv;
        }
        float other = __shfl_xor_sync(0xffffffffu, cacc, 1);
        if (halfe == 0) g_C[(size_t)i * P_ + p] = bo[p] - (cacc + other);

        #pragma unroll
        for (int g = 0; g < 2; g++) {
            uint32_t hw[4], lw[4];
            #pragma unroll
            for (int q = 0; q < 4; q++)
                split2(m[g * 8 + 2 * q], m[g * 8 + 2 * q + 1], hw[q], lw[q]);
            const size_t wofs = ((size_t)i * P_ + p) * 16 + halfe * 8 + g * 4;
            *reinterpret_cast<uint4*>(g_Mh + wofs) = make_uint4(hw[0], hw[1], hw[2], hw[3]);
            *reinterpret_cast<uint4*>(g_Ml + wofs) = make_uint4(lw[0], lw[1], lw[2], lw[3]);
        }
    }
}

// ---------------------------------------------------------------------------
// Kernel 2: HMMA m16n8k16 + ldmatrix. Prologue = pure cp.async of
// precomputed M/C/Q. Epilogue staging overlays the (dead) Q region.
// 2 CTAs per i (256 j rows each). bf16 3-split, fp32 accum.
// ---------------------------------------------------------------------------
#define ROWB 80    // bytes per padded bf16 row (32 vals + pad)
#define JR   256   // j rows per CTA
#define SROW 72    // epilogue staging row stride in floats

#define OFF_SC  0                               // 512 B
#define OFF_QH  512
#define OFF_QL  (OFF_QH + JR * ROWB)            // 20992
#define OFF_MH  (OFF_QL + JR * ROWB)            // 41472
#define OFF_ML  (OFF_MH + 128 * ROWB)           // 51712
#define SMEM_TOTAL (OFF_ML + 128 * ROWB)        // 61952
#define STG_WARP_B (16 * SROW * 4)              // 4608 B per warp (overlays QH/QL)

__global__ __launch_bounds__(256, 2)
void pair_mma_kernel(float* __restrict__ out) {  // [B][L][L][P]
    extern __shared__ char smem[];
    float* sC = reinterpret_cast<float*>(smem + OFF_SC);
    const uint32_t sbase = smem_u32(smem);

    const int bi    = blockIdx.x >> 1;   // b*L + i
    const int jbase = (blockIdx.x & 1) * JR;
    const int b     = bi >> 9;
    const int tid = threadIdx.x;
    const int wid = tid >> 5;
    const int lid = tid & 31;

    // --- prologue: cp.async C, M(hi/lo), Q(hi/lo) ---
    if (tid < 32)
        cpa16(sbase + OFF_SC + tid * 16, g_C + (size_t)bi * P_ + tid * 4);
    {
        const uint32_t* mh = g_Mh + (size_t)bi * P_ * 16;
        const uint32_t* ml = g_Ml + (size_t)bi * P_ * 16;
        #pragma unroll
        for (int it = 0; it < 2; it++) {
            const int idx = tid + 256 * it;     // 0..511 = 128 rows x 4 segs
            const int row = idx >> 2;
            const int seg = idx & 3;
            const uint32_t so = (uint32_t)row * ROWB + seg * 16u;
            cpa16(sbase + OFF_MH + so, mh + (size_t)row * 16 + seg * 4);
            cpa16(sbase + OFF_ML + so, ml + (size_t)row * 16 + seg * 4);
        }
    }
    {
        const uint32_t* qh = g_qh + ((size_t)b * L_ + jbase) * 16;
        const uint32_t* ql = g_ql + ((size_t)b * L_ + jbase) * 16;
        #pragma unroll
        for (int it = 0; it < 4; it++) {
            const int idx = tid + 256 * it;     // 0..1023 = 256 rows x 4 segs
            const int row = idx >> 2;
            const int seg = idx & 3;
            const uint32_t so = (uint32_t)row * ROWB + seg * 16u;
            cpa16(sbase + OFF_QH + so, qh + (size_t)row * 16 + seg * 4);
            cpa16(sbase + OFF_QL + so, ql + (size_t)row * 16 + seg * 4);
        }
    }
    CPA_COMMIT();
    CPA_WAIT0();
    __syncthreads();

    // --- compute: warp w -> j rows [w*32, +32) ---
    const int j0 = wid * 32;
    const int g   = lid >> 2;   // groupID 0..7
    const int tig = lid & 3;    // thread-in-group

    const int quad   = lid >> 3;
    const int within = lid & 7;
    const uint32_t rowA  = (uint32_t)((quad & 1) * 8 + within);
    const uint32_t koffA = (uint32_t)((quad >> 1) * 16);
    const uint32_t aQH = sbase + OFF_QH + (uint32_t)(j0 + rowA) * ROWB + koffA;
    const uint32_t aQL = sbase + OFF_QL + (uint32_t)(j0 + rowA) * ROWB + koffA;
    const uint32_t rowB  = (uint32_t)((quad >> 1) * 8 + within);
    const uint32_t koffB = (uint32_t)((quad & 1) * 16);
    const uint32_t bMH = sbase + OFF_MH + rowB * ROWB + koffB;
    const uint32_t bML = sbase + OFF_ML + rowB * ROWB + koffB;

    // A fragments (h-invariant), [kc][mi][4]
    uint32_t aqh[2][2][4], aql[2][2][4];
    #pragma unroll
    for (int kc = 0; kc < 2; kc++)
        #pragma unroll
        for (int mi = 0; mi < 2; mi++) {
            ldsm4(aqh[kc][mi], aQH + (uint32_t)(mi * 16 * ROWB + kc * 32));
            ldsm4(aql[kc][mi], aQL + (uint32_t)(mi * 16 * ROWB + kc * 32));
        }
    __syncthreads();   // QH/QL now dead; staging may overlay it

    float* wbuf = reinterpret_cast<float*>(smem + OFF_QH + wid * STG_WARP_B);

    #pragma unroll 1
    for (int h = 0; h < 2; h++) {
        // init accumulators with C bias
        float acc[2][8][4];
        #pragma unroll
        for (int ni = 0; ni < 8; ni++) {
            const int p = h * 64 + ni * 8 + 2 * tig;
            float2 cv = *reinterpret_cast<const float2*>(sC + p);
            #pragma unroll
            for (int mi = 0; mi < 2; mi++) {
                acc[mi][ni][0] = cv.x; acc[mi][ni][1] = cv.y;
                acc[mi][ni][2] = cv.x; acc[mi][ni][3] = cv.y;
            }
        }

        #pragma unroll
        for (int kc = 0; kc < 2; kc++) {
            #pragma unroll
            for (int np = 0; np < 4; np++) {
                const uint32_t boff = (uint32_t)((h * 64 + np * 16) * ROWB + kc * 32);
                uint32_t bh[4], bl[4];
                ldsm4(bh, bMH + boff);
                ldsm4(bl, bML + boff);
                #pragma unroll
                for (int mi = 0; mi < 2; mi++) {
                    #pragma unroll
                    for (int nn = 0; nn < 2; nn++) {
                        float* d = acc[mi][np * 2 + nn];
                        mma16(d, aqh[kc][mi], bh[2 * nn], bh[2 * nn + 1]);  // qh*mh
                        mma16(d, aqh[kc][mi], bl[2 * nn], bl[2 * nn + 1]);  // qh*ml
                        mma16(d, aql[kc][mi], bh[2 * nn], bh[2 * nn + 1]);  // ql*mh
                    }
                }
            }
        }

        // --- epilogue: smem transpose -> coalesced STG.128 ---
        #pragma unroll
        for (int mi = 0; mi < 2; mi++) {
            #pragma unroll
            for (int ni = 0; ni < 8; ni++) {
                const int col = ni * 8 + 2 * tig;
                *reinterpret_cast<float2*>(&wbuf[g * SROW + col]) =
                    make_float2(acc[mi][ni][0], acc[mi][ni][1]);
                *reinterpret_cast<float2*>(&wbuf[(g + 8) * SROW + col]) =
                    make_float2(acc[mi][ni][2], acc[mi][ni][3]);
            }
            __syncwarp();
            const int rsub = lid >> 4;           // 0..1
            const int c4i  = lid & 15;           // 0..15 float4 within 64-col half
            #pragma unroll
            for (int s = 0; s < 8; s++) {
                const int row = rsub + 2 * s;
                float4 v = *reinterpret_cast<const float4*>(&wbuf[row * SROW + c4i * 4]);
                const int j = jbase + j0 + mi * 16 + row;
                float4* dst = reinterpret_cast<float4*>(
                    out + (((size_t)bi) * L_ + j) * P_ + h * 64 + c4i * 4);
                __stcs(dst, v);
            }
            __syncwarp();
        }
    }
}

// ---------------------------------------------------------------------------
// launch
// ---------------------------------------------------------------------------
extern "C" void kernel_launch(void* const* d_in, const int* in_sizes, int n_in,
                              void* d_out, int out_size) {
    const float* seq   = (const float*)d_in[0];
    const float* gamma = (const float*)d_in[1];
    const float* beta  = (const float*)d_in[2];
    const float* Wp    = (const float*)d_in[3];
    const float* bp    = (const float*)d_in[4];
    const float* Wo    = (const float*)d_in[5];
    const float* bo    = (const float*)d_in[6];
    float* out = (float*)d_out;

    static int smem_set = 0;
    if (!smem_set) {
        cudaFuncSetAttribute(pair_mma_kernel,
                             cudaFuncAttributeMaxDynamicSharedMemorySize, SMEM_TOTAL);
        smem_set = 1;
    }

    ln_proj_kernel<<<dim3(128, 2), 256>>>(seq, gamma, beta, Wp, bp);
    prep_kernel<<<256, 256>>>(Wo, bo);
    pair_mma_kernel<<<2 * B_ * L_, 256, SMEM_TOTAL>>>(out);
}

// round 13
// speedup vs baseline: 1.0132x; 1.0132x over previous
#include <cuda_runtime.h>
#include <cuda_bf16.h>
#include <cstdint>

#define B_  2
#define L_  512
#define D_  1024
#define E_  32      // INNER
#define P_  128     // PAIR

// Global scratch (allocation-free rule: __device__ globals)
__device__ float    g_k  [B_ * L_ * E_];        // [b*L + i][e]  fp32
__device__ uint32_t g_qh [B_ * L_ * 16];        // [row][16] bf16x2 hi
__device__ uint32_t g_ql [B_ * L_ * 16];        // [row][16] bf16x2 lo
__device__ uint32_t g_Mh [B_ * L_ * P_ * 16];   // [i][p][16] bf16x2 hi
__device__ uint32_t g_Ml [B_ * L_ * P_ * 16];   // [i][p][16] bf16x2 lo
__device__ float    g_C  [B_ * L_ * P_];        // [i][p]

// ---------------------------------------------------------------------------
// helpers
// ---------------------------------------------------------------------------
__device__ __forceinline__ uint32_t smem_u32(const void* p) {
    uint32_t a;
    asm("{ .reg .u64 t; cvta.to.shared.u64 t, %1; cvt.u32.u64 %0, t; }"
        : "=r"(a) : "l"(p));
    return a;
}

__device__ __forceinline__ void mma16(float* d, const uint32_t* a, uint32_t b0, uint32_t b1) {
    asm volatile(
        "mma.sync.aligned.m16n8k16.row.col.f32.bf16.bf16.f32 "
        "{%0,%1,%2,%3}, {%4,%5,%6,%7}, {%8,%9}, {%0,%1,%2,%3};"
        : "+f"(d[0]), "+f"(d[1]), "+f"(d[2]), "+f"(d[3])
        : "r"(a[0]), "r"(a[1]), "r"(a[2]), "r"(a[3]), "r"(b0), "r"(b1));
}

__device__ __forceinline__ void ldsm4(uint32_t* r, uint32_t addr) {
    asm volatile("ldmatrix.sync.aligned.m8n8.x4.shared.b16 {%0,%1,%2,%3}, [%4];"
                 : "=r"(r[0]), "=r"(r[1]), "=r"(r[2]), "=r"(r[3]) : "r"(addr));
}

__device__ __forceinline__ void cpa16(uint32_t saddr, const void* g) {
    asm volatile("cp.async.cg.shared.global [%0], [%1], 16;"
                 :: "r"(saddr), "l"(g) : "memory");
}
#define CPA_COMMIT() asm volatile("cp.async.commit_group;" ::: "memory")
#define CPA_WAIT0()  asm volatile("cp.async.wait_group 0;" ::: "memory")

// bf16 hi/lo split of two floats, packed into two words
__device__ __forceinline__ void split2(float a, float b, uint32_t& hw, uint32_t& lw) {
    __nv_bfloat16 ah = __float2bfloat16(a);
    __nv_bfloat16 bh = __float2bfloat16(b);
    __nv_bfloat16 al = __float2bfloat16(a - __bfloat162float(ah));
    __nv_bfloat16 bl = __float2bfloat16(b - __bfloat162float(bh));
    hw = (uint32_t)__bfloat16_as_ushort(ah) | ((uint32_t)__bfloat16_as_ushort(bh) << 16);
    lw = (uint32_t)__bfloat16_as_ushort(al) | ((uint32_t)__bfloat16_as_ushort(bl) << 16);
}

// ---------------------------------------------------------------------------
// Kernel 1: LayerNorm + projection -> q (pre-split bf16 hi/lo), k (fp32)
// grid (128, 2), 256 threads: CTA = 8 rows x 32 outputs (y: q-half/k-half)
// W loads batched in explicit 8-wide prefetch chunks (MLP >= 8).
// ---------------------------------------------------------------------------
__global__ __launch_bounds__(256)
void ln_proj_kernel(const float* __restrict__ x,
                    const float* __restrict__ gamma,
                    const float* __restrict__ beta,
                    const float* __restrict__ Wp,   // [64][1024]
                    const float* __restrict__ bp) { // [64]
    __shared__ float sn[8][D_];         // 32 KB
    __shared__ float sq[8][32];
    const int tid = threadIdx.x;
    const int wid = tid >> 5;
    const int lid = tid & 31;
    const int row = blockIdx.x * 8 + wid;
    const int ohalf = blockIdx.y;       // 0 -> q outs, 1 -> k outs

    {
        const float4* xr = reinterpret_cast<const float4*>(x + (size_t)row * D_);
        float4 v[8];
        #pragma unroll
        for (int u = 0; u < 8; u++) v[u] = xr[lid + 32 * u];

        float s = 0.f;
        #pragma unroll
        for (int u = 0; u < 8; u++) s += v[u].x + v[u].y + v[u].z + v[u].w;
        #pragma unroll
        for (int o = 16; o > 0; o >>= 1) s += __shfl_xor_sync(0xffffffffu, s, o);
        const float mu = s * (1.0f / D_);

        float ss = 0.f;
        #pragma unroll
        for (int u = 0; u < 8; u++) {
            float d0 = v[u].x - mu, d1 = v[u].y - mu, d2 = v[u].z - mu, d3 = v[u].w - mu;
            ss += d0 * d0 + d1 * d1 + d2 * d2 + d3 * d3;
        }
        #pragma unroll
        for (int o = 16; o > 0; o >>= 1) ss += __shfl_xor_sync(0xffffffffu, ss, o);
        const float rs = rsqrtf(ss * (1.0f / D_) + 1e-5f);

        const float4* g4 = reinterpret_cast<const float4*>(gamma);
        const float4* b4 = reinterpret_cast<const float4*>(beta);
        #pragma unroll
        for (int u = 0; u < 8; u++) {
            float4 g = g4[lid + 32 * u];
            float4 be = b4[lid + 32 * u];
            float4 o4;
            o4.x = (v[u].x - mu) * rs * g.x + be.x;
            o4.y = (v[u].y - mu) * rs * g.y + be.y;
            o4.z = (v[u].z - mu) * rs * g.z + be.z;
            o4.w = (v[u].w - mu) * rs * g.w + be.w;
            reinterpret_cast<float4*>(sn[wid])[lid + 32 * u] = o4;
        }
    }
    __syncthreads();

    // projection: thread = (o 0..31, part 0..7); 8 rows per thread
    const int o = tid >> 3;
    const int part = tid & 7;
    const int og = ohalf * 32 + o;
    const float4* w4 = reinterpret_cast<const float4*>(Wp + (size_t)og * D_);
    float acc[8];
    #pragma unroll
    for (int r = 0; r < 8; r++) acc[r] = 0.f;

    #pragma unroll
    for (int c = 0; c < 4; c++) {
        float4 wreg[8];
        #pragma unroll
        for (int u = 0; u < 8; u++)
            wreg[u] = w4[part + 8 * (c * 8 + u)];
        #pragma unroll
        for (int u = 0; u < 8; u++) {
            const int f = part + 8 * (c * 8 + u);
            #pragma unroll
            for (int r = 0; r < 8; r++) {
                float4 a = reinterpret_cast<const float4*>(sn[r])[f];
                acc[r] += a.x * wreg[u].x + a.y * wreg[u].y
                        + a.z * wreg[u].z + a.w * wreg[u].w;
            }
        }
    }
    #pragma unroll
    for (int r = 0; r < 8; r++) {
        acc[r] += __shfl_xor_sync(0xffffffffu, acc[r], 1);
        acc[r] += __shfl_xor_sync(0xffffffffu, acc[r], 2);
        acc[r] += __shfl_xor_sync(0xffffffffu, acc[r], 4);
    }

    const int row0 = blockIdx.x * 8;
    if (ohalf == 1) {
        if (part == 0) {
            const float bias = bp[og];
            #pragma unroll
            for (int r = 0; r < 8; r++)
                g_k[(size_t)(row0 + r) * E_ + o] = acc[r] + bias;
        }
    } else {
        if (part == 0) {
            const float bias = bp[og];
            #pragma unroll
            for (int r = 0; r < 8; r++)
                sq[r][o] = acc[r] + bias;
        }
        __syncthreads();
        if (tid < 128) {
            const int r = tid >> 4;       // 0..7
            const int w = tid & 15;       // 0..15 word
            uint32_t hw, lw;
            split2(sq[r][2 * w], sq[r][2 * w + 1], hw, lw);
            g_qh[(size_t)(row0 + r) * 16 + w] = hw;
            g_ql[(size_t)(row0 + r) * 16 + w] = lw;
        }
    }
}

// ---------------------------------------------------------------------------
// Kernel 1b: precompute M_i (bf16 hi/lo) + C_i for all i.
// grid 128 x 256 thr; each block stages Wo once, serves 8 i's.
// ---------------------------------------------------------------------------
#define WOPAD 68
__global__ __launch_bounds__(256)
void prep_kernel(const float* __restrict__ Wo,   // [128][64]
                 const float* __restrict__ bo) { // [128]
    __shared__ float sWo[128 * WOPAD];  // 34816 B
    __shared__ float sk[8][E_];
    const int tid = threadIdx.x;

    {
        const float4* wsrc = reinterpret_cast<const float4*>(Wo);
        #pragma unroll
        for (int it = 0; it < 8; it++) {
            const int idx = tid + 256 * it;     // 0..2047
            const int row = idx >> 4;
            const int seg = idx & 15;
            *reinterpret_cast<float4*>(sWo + (size_t)row * WOPAD + seg * 4) = wsrc[idx];
        }
    }
    if (tid < 256) {
        const int ii = tid >> 5;
        const int e  = tid & 31;
        sk[ii][e] = g_k[(size_t)(blockIdx.x * 8 + ii) * E_ + e];
    }
    __syncthreads();

    const int p = tid >> 1;
    const int halfe = tid & 1;
    const float* wrow = sWo + (size_t)p * WOPAD;

    #pragma unroll 1
    for (int ii = 0; ii < 8; ii++) {
        const int i = blockIdx.x * 8 + ii;
        float m[16];
        float cacc = 0.f;
        #pragma unroll
        for (int u = 0; u < 16; u++) {
            const int e = halfe * 16 + u;
            float w1 = wrow[e];
            float w2 = wrow[E_ + e];
            float kv = sk[ii][e];
            m[u] = fmaf(w1, kv, w2);
            cacc += w2 * kv;
        }
        float other = __shfl_xor_sync(0xffffffffu, cacc, 1);
        if (halfe == 0) g_C[(size_t)i * P_ + p] = bo[p] - (cacc + other);

        #pragma unroll
        for (int g = 0; g < 2; g++) {
            uint32_t hw[4], lw[4];
            #pragma unroll
            for (int q = 0; q < 4; q++)
                split2(m[g * 8 + 2 * q], m[g * 8 + 2 * q + 1], hw[q], lw[q]);
            const size_t wofs = ((size_t)i * P_ + p) * 16 + halfe * 8 + g * 4;
            *reinterpret_cast<uint4*>(g_Mh + wofs) = make_uint4(hw[0], hw[1], hw[2], hw[3]);
            *reinterpret_cast<uint4*>(g_Ml + wofs) = make_uint4(lw[0], lw[1], lw[2], lw[3]);
        }
    }
}

// ---------------------------------------------------------------------------
// Kernel 2: HMMA m16n8k16 + ldmatrix. Prologue = pure cp.async of
// precomputed M/C/Q. Epilogue staging overlays the (dead) Q region.
// 2 CTAs per i (256 j rows each). bf16 3-split, fp32 accum.
// ---------------------------------------------------------------------------
#define ROWB 80    // bytes per padded bf16 row (32 vals + pad)
#define JR   256   // j rows per CTA
#define SROW 72    // epilogue staging row stride in floats

#define OFF_SC  0                               // 512 B
#define OFF_QH  512
#define OFF_QL  (OFF_QH + JR * ROWB)            // 20992
#define OFF_MH  (OFF_QL + JR * ROWB)            // 41472
#define OFF_ML  (OFF_MH + 128 * ROWB)           // 51712
#define SMEM_TOTAL (OFF_ML + 128 * ROWB)        // 61952
#define STG_WARP_B (16 * SROW * 4)              // 4608 B per warp (overlays QH/QL)

__global__ __launch_bounds__(256, 2)
void pair_mma_kernel(float* __restrict__ out) {  // [B][L][L][P]
    extern __shared__ char smem[];
    float* sC = reinterpret_cast<float*>(smem + OFF_SC);
    const uint32_t sbase = smem_u32(smem);

    const int bi    = blockIdx.x >> 1;   // b*L + i
    const int jbase = (blockIdx.x & 1) * JR;
    const int b     = bi >> 9;
    const int tid = threadIdx.x;
    const int wid = tid >> 5;
    const int lid = tid & 31;

    // --- prologue: cp.async C, M(hi/lo), Q(hi/lo) ---
    if (tid < 32)
        cpa16(sbase + OFF_SC + tid * 16, g_C + (size_t)bi * P_ + tid * 4);
    {
        const uint32_t* mh = g_Mh + (size_t)bi * P_ * 16;
        const uint32_t* ml = g_Ml + (size_t)bi * P_ * 16;
        #pragma unroll
        for (int it = 0; it < 2; it++) {
            const int idx = tid + 256 * it;     // 0..511 = 128 rows x 4 segs
            const int row = idx >> 2;
            const int seg = idx & 3;
            const uint32_t so = (uint32_t)row * ROWB + seg * 16u;
            cpa16(sbase + OFF_MH + so, mh + (size_t)row * 16 + seg * 4);
            cpa16(sbase + OFF_ML + so, ml + (size_t)row * 16 + seg * 4);
        }
    }
    {
        const uint32_t* qh = g_qh + ((size_t)b * L_ + jbase) * 16;
        const uint32_t* ql = g_ql + ((size_t)b * L_ + jbase) * 16;
        #pragma unroll
        for (int it = 0; it < 4; it++) {
            const int idx = tid + 256 * it;     // 0..1023 = 256 rows x 4 segs
            const int row = idx >> 2;
            const int seg = idx & 3;
            const uint32_t so = (uint32_t)row * ROWB + seg * 16u;
            cpa16(sbase + OFF_QH + so, qh + (size_t)row * 16 + seg * 4);
            cpa16(sbase + OFF_QL + so, ql + (size_t)row * 16 + seg * 4);
        }
    }
    CPA_COMMIT();
    CPA_WAIT0();
    __syncthreads();

    // --- compute: warp w -> j rows [w*32, +32) ---
    const int j0 = wid * 32;
    const int g   = lid >> 2;   // groupID 0..7
    const int tig = lid & 3;    // thread-in-group

    const int quad   = lid >> 3;
    const int within = lid & 7;
    const uint32_t rowA  = (uint32_t)((quad & 1) * 8 + within);
    const uint32_t koffA = (uint32_t)((quad >> 1) * 16);
    const uint32_t aQH = sbase + OFF_QH + (uint32_t)(j0 + rowA) * ROWB + koffA;
    const uint32_t aQL = sbase + OFF_QL + (uint32_t)(j0 + rowA) * ROWB + koffA;
    const uint32_t rowB  = (uint32_t)((quad >> 1) * 8 + within);
    const uint32_t koffB = (uint32_t)((quad & 1) * 16);
    const uint32_t bMH = sbase + OFF_MH + rowB * ROWB + koffB;
    const uint32_t bML = sbase + OFF_ML + rowB * ROWB + koffB;

    // A fragments (h-invariant), [kc][mi][4]
    uint32_t aqh[2][2][4], aql[2][2][4];
    #pragma unroll
    for (int kc = 0; kc < 2; kc++)
        #pragma unroll
        for (int mi = 0; mi < 2; mi++) {
            ldsm4(aqh[kc][mi], aQH + (uint32_t)(mi * 16 * ROWB + kc * 32));
            ldsm4(aql[kc][mi], aQL + (uint32_t)(mi * 16 * ROWB + kc * 32));
        }
    __syncthreads();   // QH/QL now dead; staging may overlay it

    float* wbuf = reinterpret_cast<float*>(smem + OFF_QH + wid * STG_WARP_B);

    #pragma unroll 1
    for (int h = 0; h < 2; h++) {
        // init accumulators with C bias
        float acc[2][8][4];
        #pragma unroll
        for (int ni = 0; ni < 8; ni++) {
            const int p = h * 64 + ni * 8 + 2 * tig;
            float2 cv = *reinterpret_cast<const float2*>(sC + p);
            #pragma unroll
            for (int mi = 0; mi < 2; mi++) {
                acc[mi][ni][0] = cv.x; acc[mi][ni][1] = cv.y;
                acc[mi][ni][2] = cv.x; acc[mi][ni][3] = cv.y;
            }
        }

        #pragma unroll
        for (int kc = 0; kc < 2; kc++) {
            #pragma unroll
            for (int np = 0; np < 4; np++) {
                const uint32_t boff = (uint32_t)((h * 64 + np * 16) * ROWB + kc * 32);
                uint32_t bh[4], bl[4];
                ldsm4(bh, bMH + boff);
                ldsm4(bl, bML + boff);
                #pragma unroll
                for (int mi = 0; mi < 2; mi++) {
                    #pragma unroll
                    for (int nn = 0; nn < 2; nn++) {
                        float* d = acc[mi][np * 2 + nn];
                        mma16(d, aqh[kc][mi], bh[2 * nn], bh[2 * nn + 1]);  // qh*mh
                        mma16(d, aqh[kc][mi], bl[2 * nn], bl[2 * nn + 1]);  // qh*ml
                        mma16(d, aql[kc][mi], bh[2 * nn], bh[2 * nn + 1]);  // ql*mh
                    }
                }
            }
        }

        // --- epilogue: smem transpose -> coalesced STG.128 ---
        #pragma unroll
        for (int mi = 0; mi < 2; mi++) {
            #pragma unroll
            for (int ni = 0; ni < 8; ni++) {
                const int col = ni * 8 + 2 * tig;
                *reinterpret_cast<float2*>(&wbuf[g * SROW + col]) =
                    make_float2(acc[mi][ni][0], acc[mi][ni][1]);
                *reinterpret_cast<float2*>(&wbuf[(g + 8) * SROW + col]) =
                    make_float2(acc[mi][ni][2], acc[mi][ni][3]);
            }
            __syncwarp();
            const int rsub = lid >> 4;           // 0..1
            const int c4i  = lid & 15;           // 0..15 float4 within 64-col half
            #pragma unroll
            for (int s = 0; s < 8; s++) {
                const int row = rsub + 2 * s;
                float4 v = *reinterpret_cast<const float4*>(&wbuf[row * SROW + c4i * 4]);
                const int j = jbase + j0 + mi * 16 + row;
                float4* dst = reinterpret_cast<float4*>(
                    out + (((size_t)bi) * L_ + j) * P_ + h * 64 + c4i * 4);
                __stcs(dst, v);
            }
            __syncwarp();
        }
    }
}

// ---------------------------------------------------------------------------
// launch
// ---------------------------------------------------------------------------
extern "C" void kernel_launch(void* const* d_in, const int* in_sizes, int n_in,
                              void* d_out, int out_size) {
    const float* seq   = (const float*)d_in[0];
    const float* gamma = (const float*)d_in[1];
    const float* beta  = (const float*)d_in[2];
    const float* Wp    = (const float*)d_in[3];
    const float* bp    = (const float*)d_in[4];
    const float* Wo    = (const float*)d_in[5];
    const float* bo    = (const float*)d_in[6];
    float* out = (float*)d_out;

    static int smem_set = 0;
    if (!smem_set) {
        cudaFuncSetAttribute(pair_mma_kernel,
                             cudaFuncAttributeMaxDynamicSharedMemorySize, SMEM_TOTAL);
        smem_set = 1;
    }

    ln_proj_kernel<<<dim3(128, 2), 256>>>(seq, gamma, beta, Wp, bp);
    prep_kernel<<<128, 256>>>(Wo, bo);
    pair_mma_kernel<<<2 * B_ * L_, 256, SMEM_TOTAL>>>(out);
}